// round 1
// baseline (speedup 1.0000x reference)
#include <cuda_runtime.h>

// Problem constants (from reference)
#define NV 100000      // vertices
#define TT 128         // temporal depth
#define NE_MAX 1600000 // edges
#define NCHUNK 98      // ceil(NV / 1024)

// ---------------- static device scratch (allocation-free) ----------------
__device__ float g_xbuf[2][(size_t)NV * TT]; // ping-pong feature buffers (2 x 51.2MB)
__device__ int   g_deg[NV];
__device__ int   g_off[NV + 1];
__device__ int   g_cur[NV];
__device__ int   g_srcs[NE_MAX];
__device__ float g_inv[NV];
__device__ int   g_part[NCHUNK];

// ---------------- CSR construction ----------------
__global__ void k_zero() {
    int i = blockIdx.x * blockDim.x + threadIdx.x;
    if (i < NV) g_deg[i] = 0;
}

__global__ void k_hist(const int* __restrict__ dst, int E) {
    int i = blockIdx.x * blockDim.x + threadIdx.x;
    if (i < E) atomicAdd(&g_deg[dst[i]], 1);
}

// per-chunk (1024) Hillis-Steele exclusive scan
__global__ void k_scanA() {
    __shared__ int sh[1024];
    int tid = threadIdx.x;
    int idx = blockIdx.x * 1024 + tid;
    int v = (idx < NV) ? g_deg[idx] : 0;
    sh[tid] = v;
    __syncthreads();
    #pragma unroll
    for (int d = 1; d < 1024; d <<= 1) {
        int t = (tid >= d) ? sh[tid - d] : 0;
        __syncthreads();
        sh[tid] += t;
        __syncthreads();
    }
    if (idx < NV) g_off[idx] = sh[tid] - v; // exclusive within chunk
    if (tid == 1023) g_part[blockIdx.x] = sh[1023];
}

// serial scan of 98 chunk totals (trivial)
__global__ void k_scanB() {
    int run = 0;
    for (int b = 0; b < NCHUNK; b++) {
        int t = g_part[b];
        g_part[b] = run;
        run += t;
    }
}

__global__ void k_scanC(int E) {
    int i = blockIdx.x * blockDim.x + threadIdx.x;
    if (i < NV) {
        int v = g_off[i] + g_part[i >> 10];
        g_off[i] = v;
        g_cur[i] = v;
        g_inv[i] = 1.0f / (float)(g_deg[i] + 1); // +1 self loop
    }
    if (i == 0) g_off[NV] = E;
}

__global__ void k_scatter(const int* __restrict__ src, const int* __restrict__ dst, int E) {
    int i = blockIdx.x * blockDim.x + threadIdx.x;
    if (i < E) {
        int d = dst[i];
        int p = atomicAdd(&g_cur[d], 1);
        g_srcs[p] = src[i];
    }
}

// ---------------- fused layer: mean-aggregate -> conv1d(K=9) -> relu ----------------
// conv and mean-agg commute exactly (linear ops; bias survives the mean),
// so relu(agg(conv(x))) == relu(conv(agg(x))).
// One warp per destination node; each lane owns 4 consecutive t values (float4).
__global__ void __launch_bounds__(256) k_layer(
    const float* __restrict__ xext, int in_sel, int out_sel,
    const float* __restrict__ cw, const float* __restrict__ cb)
{
    const float4* __restrict__ xin =
        (const float4*)((in_sel < 0) ? xext : g_xbuf[in_sel]);
    float4* __restrict__ xout = (float4*)g_xbuf[out_sel];

    int lane = threadIdx.x & 31;
    int n = blockIdx.x * 8 + (threadIdx.x >> 5);

    float w[9];
    #pragma unroll
    for (int k = 0; k < 9; k++) w[k] = __ldg(cw + k);
    float bias = __ldg(cb);

    size_t rbase = (size_t)n * 32 + lane;
    float4 acc = xin[rbase]; // self loop
    int jb = g_off[n], je = g_off[n + 1];
    float inv = g_inv[n];

    int j = jb;
    for (; j + 4 <= je; j += 4) {
        int s0 = g_srcs[j], s1 = g_srcs[j + 1], s2 = g_srcs[j + 2], s3 = g_srcs[j + 3];
        float4 v0 = xin[(size_t)s0 * 32 + lane];
        float4 v1 = xin[(size_t)s1 * 32 + lane];
        float4 v2 = xin[(size_t)s2 * 32 + lane];
        float4 v3 = xin[(size_t)s3 * 32 + lane];
        acc.x += (v0.x + v1.x) + (v2.x + v3.x);
        acc.y += (v0.y + v1.y) + (v2.y + v3.y);
        acc.z += (v0.z + v1.z) + (v2.z + v3.z);
        acc.w += (v0.w + v1.w) + (v2.w + v3.w);
    }
    for (; j < je; ++j) {
        float4 v = xin[(size_t)g_srcs[j] * 32 + lane];
        acc.x += v.x; acc.y += v.y; acc.z += v.z; acc.w += v.w;
    }

    acc.x *= inv; acc.y *= inv; acc.z *= inv; acc.w *= inv;

    // conv halo via register shuffle (no shared memory).
    // v[4..7] = own 4 t-values; v[0..3] = left lane's; v[8..11] = right lane's.
    float v[12];
    v[4] = acc.x; v[5] = acc.y; v[6] = acc.z; v[7] = acc.w;
    v[0] = __shfl_up_sync(0xffffffffu, acc.x, 1);
    v[1] = __shfl_up_sync(0xffffffffu, acc.y, 1);
    v[2] = __shfl_up_sync(0xffffffffu, acc.z, 1);
    v[3] = __shfl_up_sync(0xffffffffu, acc.w, 1);
    v[8]  = __shfl_down_sync(0xffffffffu, acc.x, 1);
    v[9]  = __shfl_down_sync(0xffffffffu, acc.y, 1);
    v[10] = __shfl_down_sync(0xffffffffu, acc.z, 1);
    v[11] = __shfl_down_sync(0xffffffffu, acc.w, 1);
    if (lane == 0)  { v[0] = 0.f; v[1] = 0.f; v[2] = 0.f; v[3] = 0.f; }     // 'same' padding
    if (lane == 31) { v[8] = 0.f; v[9] = 0.f; v[10] = 0.f; v[11] = 0.f; }

    float4 res;
    #pragma unroll
    for (int i = 0; i < 4; i++) {
        float o = bias;
        #pragma unroll
        for (int k = 0; k < 9; k++) o = fmaf(v[i + k], w[k], o); // cross-correlation
        ((float*)&res)[i] = fmaxf(o, 0.0f);
    }
    xout[rbase] = res;
}

// ---------------- final projection: out[t,c] = b[c] + sum_n xflat[t*N+n]*W[c*N+n] --------
// x.reshape(T,N) on a row-major [N,T] array is a flat reinterpretation -> contiguous reads.
__global__ void __launch_bounds__(512) k_final(
    const float* __restrict__ W, const float* __restrict__ bo, float* __restrict__ out)
{
    const float* __restrict__ xr = g_xbuf[0] + (size_t)blockIdx.x * NV;
    float a0 = 0.f, a1 = 0.f, a2 = 0.f;
    for (int n = threadIdx.x; n < NV; n += 512) {
        float v = xr[n];
        a0 = fmaf(v, __ldg(W + n), a0);
        a1 = fmaf(v, __ldg(W + NV + n), a1);
        a2 = fmaf(v, __ldg(W + 2 * NV + n), a2);
    }
    #pragma unroll
    for (int o = 16; o; o >>= 1) {
        a0 += __shfl_down_sync(0xffffffffu, a0, o);
        a1 += __shfl_down_sync(0xffffffffu, a1, o);
        a2 += __shfl_down_sync(0xffffffffu, a2, o);
    }
    __shared__ float sh[16][3];
    int lane = threadIdx.x & 31, wid = threadIdx.x >> 5;
    if (lane == 0) { sh[wid][0] = a0; sh[wid][1] = a1; sh[wid][2] = a2; }
    __syncthreads();
    if (wid == 0) {
        a0 = (lane < 16) ? sh[lane][0] : 0.f;
        a1 = (lane < 16) ? sh[lane][1] : 0.f;
        a2 = (lane < 16) ? sh[lane][2] : 0.f;
        #pragma unroll
        for (int o = 8; o; o >>= 1) {
            a0 += __shfl_down_sync(0xffffffffu, a0, o);
            a1 += __shfl_down_sync(0xffffffffu, a1, o);
            a2 += __shfl_down_sync(0xffffffffu, a2, o);
        }
        if (lane == 0) {
            out[blockIdx.x * 3 + 0] = a0 + __ldg(bo + 0);
            out[blockIdx.x * 3 + 1] = a1 + __ldg(bo + 1);
            out[blockIdx.x * 3 + 2] = a2 + __ldg(bo + 2);
        }
    }
}

// ---------------- launch ----------------
extern "C" void kernel_launch(void* const* d_in, const int* in_sizes, int n_in,
                              void* d_out, int out_size)
{
    const float* x  = (const float*)d_in[0];
    const int*   ei = (const int*)d_in[1];
    const float* cw = (const float*)d_in[2]; // [L,1,1,K]
    const float* cb = (const float*)d_in[3]; // [L,1]
    const float* Wo = (const float*)d_in[4]; // [3,N]
    const float* bo = (const float*)d_in[5]; // [3]
    float* out = (float*)d_out;

    int E = in_sizes[1] / 2;
    const int* src = ei;
    const int* dst = ei + E;

    // CSR by destination (rebuilt every call; deterministic work)
    k_zero<<<(NV + 255) / 256, 256>>>();
    k_hist<<<(E + 255) / 256, 256>>>(dst, E);
    k_scanA<<<NCHUNK, 1024>>>();
    k_scanB<<<1, 1>>>();
    k_scanC<<<(NV + 255) / 256, 256>>>(E);
    k_scatter<<<(E + 255) / 256, 256>>>(src, dst, E);

    // 3 fused layers: agg -> conv -> relu, ping-pong buffers
    k_layer<<<NV / 8, 256>>>(x, -1, 0, cw + 0, cb + 0);
    k_layer<<<NV / 8, 256>>>(nullptr, 0, 1, cw + 9, cb + 1);
    k_layer<<<NV / 8, 256>>>(nullptr, 1, 0, cw + 18, cb + 2);

    // final [T,3] projection
    k_final<<<TT, 512>>>(Wo, bo, out);
}

// round 2
// speedup vs baseline: 1.4259x; 1.4259x over previous
#include <cuda_runtime.h>
#include <cuda_fp16.h>

// Problem constants (from reference)
#define NV 100000      // vertices
#define TT 128         // temporal depth
#define NE_MAX 1600000 // edges
#define NCHUNK 98      // ceil(NV / 1024)

// ---------------- static device scratch (allocation-free) ----------------
__device__ __half g_hbuf[2][(size_t)NV * TT]; // ping-pong fp16 feature buffers (2 x 25.6MB)
__device__ int    g_deg[NV];
__device__ int    g_off[NV + 1];
__device__ int    g_cur[NV];
__device__ int    g_srcs[NE_MAX];
__device__ float  g_inv[NV];
__device__ int    g_part[NCHUNK];

// ---------------- helpers ----------------
__device__ __forceinline__ float4 h2f4(uint2 p) {
    __half2 a = *(__half2*)&p.x;
    __half2 b = *(__half2*)&p.y;
    float2 fa = __half22float2(a);
    float2 fb = __half22float2(b);
    return make_float4(fa.x, fa.y, fb.x, fb.y);
}
__device__ __forceinline__ uint2 f4h2(float4 v) {
    __half2 a = __floats2half2_rn(v.x, v.y);
    __half2 b = __floats2half2_rn(v.z, v.w);
    uint2 r;
    r.x = *(unsigned*)&a;
    r.y = *(unsigned*)&b;
    return r;
}

// ---------------- input conversion fp32 -> fp16 ----------------
__global__ void k_cvt(const float4* __restrict__ x) {
    int i = blockIdx.x * 256 + threadIdx.x; // NV*TT/4 = 3.2M
    ((uint2*)g_hbuf[0])[i] = f4h2(x[i]);
}

// ---------------- CSR construction ----------------
__global__ void k_zero() {
    int i = blockIdx.x * blockDim.x + threadIdx.x;
    if (i < NV) g_deg[i] = 0;
}

__global__ void k_hist(const int* __restrict__ dst, int E) {
    int i = blockIdx.x * blockDim.x + threadIdx.x;
    if (i < E) atomicAdd(&g_deg[dst[i]], 1);
}

// per-chunk (1024) Hillis-Steele exclusive scan
__global__ void k_scanA() {
    __shared__ int sh[1024];
    int tid = threadIdx.x;
    int idx = blockIdx.x * 1024 + tid;
    int v = (idx < NV) ? g_deg[idx] : 0;
    sh[tid] = v;
    __syncthreads();
    #pragma unroll
    for (int d = 1; d < 1024; d <<= 1) {
        int t = (tid >= d) ? sh[tid - d] : 0;
        __syncthreads();
        sh[tid] += t;
        __syncthreads();
    }
    if (idx < NV) g_off[idx] = sh[tid] - v; // exclusive within chunk
    if (tid == 1023) g_part[blockIdx.x] = sh[1023];
}

// parallel scan of the 98 chunk totals (was a 8.4us serial kernel)
__global__ void k_scanB() {
    __shared__ int sh[128];
    int tid = threadIdx.x;
    int v = (tid < NCHUNK) ? g_part[tid] : 0;
    sh[tid] = v;
    __syncthreads();
    #pragma unroll
    for (int d = 1; d < 128; d <<= 1) {
        int t = (tid >= d) ? sh[tid - d] : 0;
        __syncthreads();
        sh[tid] += t;
        __syncthreads();
    }
    if (tid < NCHUNK) g_part[tid] = sh[tid] - v; // exclusive
}

__global__ void k_scanC(int E) {
    int i = blockIdx.x * blockDim.x + threadIdx.x;
    if (i < NV) {
        int v = g_off[i] + g_part[i >> 10];
        g_off[i] = v;
        g_cur[i] = v;
        g_inv[i] = 1.0f / (float)(g_deg[i] + 1); // +1 self loop
    }
    if (i == 0) g_off[NV] = E;
}

__global__ void k_scatter(const int* __restrict__ src, const int* __restrict__ dst, int E) {
    int i = blockIdx.x * blockDim.x + threadIdx.x;
    if (i < E) {
        int d = dst[i];
        int p = atomicAdd(&g_cur[d], 1);
        g_srcs[p] = src[i];
    }
}

// ---------------- fused layer: mean-aggregate -> conv1d(K=9) -> relu ----------------
// conv and mean-agg commute exactly (linear; bias survives the mean), so
// relu(agg(conv(x))) == relu(conv(agg(x))). One warp per destination node;
// each lane owns 4 consecutive t values (one uint2 = 4 fp16). fp32 accumulate.
__global__ void __launch_bounds__(256) k_layer(
    int in_sel, int out_sel,
    const float* __restrict__ cw, const float* __restrict__ cb)
{
    const uint2* __restrict__ xin = (const uint2*)g_hbuf[in_sel];
    uint2* __restrict__ xout = (uint2*)g_hbuf[out_sel];

    int lane = threadIdx.x & 31;
    int n = blockIdx.x * 8 + (threadIdx.x >> 5);

    float w[9];
    #pragma unroll
    for (int k = 0; k < 9; k++) w[k] = __ldg(cw + k);
    float bias = __ldg(cb);

    size_t rbase = (size_t)n * 32 + lane; // 32 uint2 per row of 128 fp16
    float4 acc = h2f4(xin[rbase]); // self loop
    int jb = g_off[n], je = g_off[n + 1];
    float inv = g_inv[n];

    int j = jb;
    for (; j + 4 <= je; j += 4) {
        int s0 = g_srcs[j], s1 = g_srcs[j + 1], s2 = g_srcs[j + 2], s3 = g_srcs[j + 3];
        uint2 p0 = xin[(size_t)s0 * 32 + lane];
        uint2 p1 = xin[(size_t)s1 * 32 + lane];
        uint2 p2 = xin[(size_t)s2 * 32 + lane];
        uint2 p3 = xin[(size_t)s3 * 32 + lane];
        float4 v0 = h2f4(p0), v1 = h2f4(p1), v2 = h2f4(p2), v3 = h2f4(p3);
        acc.x += (v0.x + v1.x) + (v2.x + v3.x);
        acc.y += (v0.y + v1.y) + (v2.y + v3.y);
        acc.z += (v0.z + v1.z) + (v2.z + v3.z);
        acc.w += (v0.w + v1.w) + (v2.w + v3.w);
    }
    for (; j < je; ++j) {
        float4 v = h2f4(xin[(size_t)g_srcs[j] * 32 + lane]);
        acc.x += v.x; acc.y += v.y; acc.z += v.z; acc.w += v.w;
    }

    acc.x *= inv; acc.y *= inv; acc.z *= inv; acc.w *= inv;

    // conv halo via register shuffle (no shared memory).
    float v[12];
    v[4] = acc.x; v[5] = acc.y; v[6] = acc.z; v[7] = acc.w;
    v[0] = __shfl_up_sync(0xffffffffu, acc.x, 1);
    v[1] = __shfl_up_sync(0xffffffffu, acc.y, 1);
    v[2] = __shfl_up_sync(0xffffffffu, acc.z, 1);
    v[3] = __shfl_up_sync(0xffffffffu, acc.w, 1);
    v[8]  = __shfl_down_sync(0xffffffffu, acc.x, 1);
    v[9]  = __shfl_down_sync(0xffffffffu, acc.y, 1);
    v[10] = __shfl_down_sync(0xffffffffu, acc.z, 1);
    v[11] = __shfl_down_sync(0xffffffffu, acc.w, 1);
    if (lane == 0)  { v[0] = 0.f; v[1] = 0.f; v[2] = 0.f; v[3] = 0.f; }  // 'same' pad
    if (lane == 31) { v[8] = 0.f; v[9] = 0.f; v[10] = 0.f; v[11] = 0.f; }

    float4 res;
    #pragma unroll
    for (int i = 0; i < 4; i++) {
        float o = bias;
        #pragma unroll
        for (int k = 0; k < 9; k++) o = fmaf(v[i + k], w[k], o); // cross-correlation
        ((float*)&res)[i] = fmaxf(o, 0.0f);
    }
    xout[rbase] = f4h2(res);
}

// ---------------- final projection ----------------
// x.reshape(T,N) on row-major [N,T] is a flat reinterpretation:
// out[t,c] = b[c] + sum_n hflat[t*N+n] * W[c*N+n]; both sides contiguous in n.
// Grid (32 t-tiles of 4) x (8 n-chunks); accumulate fp32, atomicAdd partials.
#define TTILE 4
#define NCHF 8
__global__ void k_init_out(const float* __restrict__ bo, float* __restrict__ out) {
    int i = threadIdx.x; // 384 = TT*3
    out[i] = __ldg(bo + (i % 3));
}

__global__ void __launch_bounds__(512) k_final(
    const float* __restrict__ W, float* __restrict__ out)
{
    const __half* __restrict__ h = g_hbuf[1];
    int t0 = blockIdx.x * TTILE;
    const int nper = NV / NCHF; // 12500
    int n0 = blockIdx.y * nper;

    float acc[TTILE][3];
    #pragma unroll
    for (int t = 0; t < TTILE; t++)
        #pragma unroll
        for (int c = 0; c < 3; c++) acc[t][c] = 0.f;

    for (int n = n0 + threadIdx.x; n < n0 + nper; n += 512) {
        float w0 = __ldg(W + n);
        float w1 = __ldg(W + NV + n);
        float w2 = __ldg(W + 2 * NV + n);
        #pragma unroll
        for (int t = 0; t < TTILE; t++) {
            float v = __half2float(h[(size_t)(t0 + t) * NV + n]);
            acc[t][0] = fmaf(v, w0, acc[t][0]);
            acc[t][1] = fmaf(v, w1, acc[t][1]);
            acc[t][2] = fmaf(v, w2, acc[t][2]);
        }
    }

    // warp reduce then block reduce in smem, then 12 atomics per block
    #pragma unroll
    for (int t = 0; t < TTILE; t++)
        #pragma unroll
        for (int c = 0; c < 3; c++)
            #pragma unroll
            for (int o = 16; o; o >>= 1)
                acc[t][c] += __shfl_down_sync(0xffffffffu, acc[t][c], o);

    __shared__ float sh[16][TTILE][3];
    int lane = threadIdx.x & 31, wid = threadIdx.x >> 5;
    if (lane == 0)
        #pragma unroll
        for (int t = 0; t < TTILE; t++)
            #pragma unroll
            for (int c = 0; c < 3; c++) sh[wid][t][c] = acc[t][c];
    __syncthreads();
    if (wid == 0 && lane < 12) {
        int t = lane >> 2;        // pairs: handle 12 outputs with 12 lanes
        int c = lane & 3;
        if (c < 3) {
            float s = 0.f;
            #pragma unroll
            for (int wgi = 0; wgi < 16; wgi++) s += sh[wgi][t][c];
            // lane covers (t in 0..2, c in 0..2) -> need t in 0..3: remap
            atomicAdd(&out[(t0 + t) * 3 + c], s);
        }
    }
    // cover t=3 (lanes 12..14)
    if (wid == 0 && lane >= 12 && lane < 15) {
        int c = lane - 12;
        float s = 0.f;
        #pragma unroll
        for (int wgi = 0; wgi < 16; wgi++) s += sh[wgi][3][c];
        atomicAdd(&out[(t0 + 3) * 3 + c], s);
    }
}

// ---------------- launch ----------------
extern "C" void kernel_launch(void* const* d_in, const int* in_sizes, int n_in,
                              void* d_out, int out_size)
{
    const float* x  = (const float*)d_in[0];
    const int*   ei = (const int*)d_in[1];
    const float* cw = (const float*)d_in[2]; // [L,1,1,K]
    const float* cb = (const float*)d_in[3]; // [L,1]
    const float* Wo = (const float*)d_in[4]; // [3,N]
    const float* bo = (const float*)d_in[5]; // [3]
    float* out = (float*)d_out;

    int E = in_sizes[1] / 2;
    const int* src = ei;
    const int* dst = ei + E;

    // input fp32 -> fp16
    k_cvt<<<NV * TT / 4 / 256, 256>>>((const float4*)x);

    // CSR by destination (rebuilt every call; deterministic work)
    k_zero<<<(NV + 255) / 256, 256>>>();
    k_hist<<<(E + 255) / 256, 256>>>(dst, E);
    k_scanA<<<NCHUNK, 1024>>>();
    k_scanB<<<1, 128>>>();
    k_scanC<<<(NV + 255) / 256, 256>>>(E);
    k_scatter<<<(E + 255) / 256, 256>>>(src, dst, E);

    // 3 fused layers: agg -> conv -> relu, ping-pong fp16 buffers
    k_layer<<<NV / 8, 256>>>(0, 1, cw + 0, cb + 0);
    k_layer<<<NV / 8, 256>>>(1, 0, cw + 9, cb + 1);
    k_layer<<<NV / 8, 256>>>(0, 1, cw + 18, cb + 2);

    // final [T,3] projection
    k_init_out<<<1, TT * 3>>>(bo, out);
    k_final<<<dim3(TT / TTILE, NCHF), 512>>>(Wo, out);
}

// round 3
// speedup vs baseline: 1.6091x; 1.1285x over previous
#include <cuda_runtime.h>
#include <cuda_fp16.h>

// Problem constants (from reference)
#define NV 100000      // vertices
#define TT 128         // temporal depth
#define NE_MAX 1600000 // edges
#define NCHUNK 98      // ceil(NV / 1024)

// ---------------- static device scratch (allocation-free) ----------------
__device__ __half g_hbuf[2][(size_t)NV * TT]; // ping-pong fp16 feature buffers (2 x 25.6MB)
__device__ int    g_deg[NV];
__device__ int    g_off[NV + 1];
__device__ int    g_cur[NV];
__device__ int    g_srcs[NE_MAX];            // stores src*16 (uint4-row units, premultiplied)
__device__ float  g_inv[NV];
__device__ int    g_part[NCHUNK];

// ---------------- helpers ----------------
__device__ __forceinline__ uint2 f4h2(float4 v) {
    __half2 a = __floats2half2_rn(v.x, v.y);
    __half2 b = __floats2half2_rn(v.z, v.w);
    uint2 r;
    r.x = *(unsigned*)&a;
    r.y = *(unsigned*)&b;
    return r;
}

// ---------------- input conversion fp32 -> fp16 (+ fused deg zeroing) ----------------
__global__ void k_cvt(const float4* __restrict__ x) {
    int i = blockIdx.x * 256 + threadIdx.x; // NV*TT/4 = 3.2M
    ((uint2*)g_hbuf[0])[i] = f4h2(x[i]);
    if (i < NV) g_deg[i] = 0;
}

// ---------------- CSR construction ----------------
__global__ void k_hist(const int* __restrict__ dst, int E) {
    int i = blockIdx.x * blockDim.x + threadIdx.x;
    if (i < E) atomicAdd(&g_deg[dst[i]], 1);
}

// per-chunk (1024) exclusive scan via warp shuffles (2 syncthreads total)
__global__ void k_scanA() {
    __shared__ int warp_tot[32];
    int tid = threadIdx.x;
    int lane = tid & 31, wid = tid >> 5;
    int idx = blockIdx.x * 1024 + tid;
    int v = (idx < NV) ? g_deg[idx] : 0;

    // warp inclusive scan
    int inc = v;
    #pragma unroll
    for (int d = 1; d < 32; d <<= 1) {
        int t = __shfl_up_sync(0xffffffffu, inc, d);
        if (lane >= d) inc += t;
    }
    if (lane == 31) warp_tot[wid] = inc;
    __syncthreads();
    if (wid == 0) {
        int wv = warp_tot[lane];
        int winc = wv;
        #pragma unroll
        for (int d = 1; d < 32; d <<= 1) {
            int t = __shfl_up_sync(0xffffffffu, winc, d);
            if (lane >= d) winc += t;
        }
        warp_tot[lane] = winc - wv; // exclusive warp prefix
        if (lane == 31) g_part[blockIdx.x] = winc; // chunk total
    }
    __syncthreads();
    if (idx < NV) g_off[idx] = inc - v + warp_tot[wid]; // exclusive within chunk
}

// fused: per-block prefix over chunk totals + finalize offsets/inv/cur
__global__ void k_scanC(int E) {
    __shared__ int chunk_pre;
    int tid = threadIdx.x;
    int bid = blockIdx.x;
    if (tid < 32) {
        int s = 0;
        for (int j = tid; j < bid; j += 32) s += g_part[j];
        #pragma unroll
        for (int o = 16; o; o >>= 1) s += __shfl_down_sync(0xffffffffu, s, o);
        if (tid == 0) chunk_pre = s;
    }
    __syncthreads();
    int idx = bid * 1024 + tid;
    if (idx < NV) {
        int v = g_off[idx] + chunk_pre;
        g_off[idx] = v;
        g_cur[idx] = v;
        g_inv[idx] = 1.0f / (float)(g_deg[idx] + 1); // +1 self loop
    }
    if (idx == 0) g_off[NV] = E;
}

__global__ void k_scatter(const int* __restrict__ src, const int* __restrict__ dst, int E) {
    int i = blockIdx.x * blockDim.x + threadIdx.x;
    if (i < E) {
        int d = dst[i];
        int p = atomicAdd(&g_cur[d], 1);
        g_srcs[p] = src[i] * 16; // premultiplied: uint4-row units
    }
}

// ---------------- fused layer: mean-aggregate -> conv1d(K=9) -> relu ----------------
// conv and mean-agg commute exactly (linear; bias survives the mean), so
// relu(agg(conv(x))) == relu(conv(agg(x))).
// HALF-WARP per node: 16 lanes, each lane owns 8 consecutive t (one uint4 = 8 fp16).
// LDG.128 gathers, fp32 accumulation, conv halo via width-16 shuffles.
__global__ void __launch_bounds__(256) k_layer(
    int in_sel, int out_sel,
    const float* __restrict__ cw, const float* __restrict__ cb)
{
    const uint4* __restrict__ xin = (const uint4*)g_hbuf[in_sel];
    uint4* __restrict__ xout = (uint4*)g_hbuf[out_sel];

    int lane  = threadIdx.x & 31;
    int slane = lane & 15;                         // lane within half-warp
    int n = blockIdx.x * 16 + ((threadIdx.x >> 5) << 1) + (lane >> 4);

    float w[9];
    #pragma unroll
    for (int k = 0; k < 9; k++) w[k] = __ldg(cw + k);
    float bias = __ldg(cb);

    unsigned rbase = (unsigned)n * 16u + (unsigned)slane; // uint4 units (32-bit math)

    float acc[8];
    { // self loop
        uint4 p = xin[rbase];
        const __half2* h = (const __half2*)&p;
        #pragma unroll
        for (int q = 0; q < 4; q++) {
            float2 f = __half22float2(h[q]);
            acc[2 * q] = f.x; acc[2 * q + 1] = f.y;
        }
    }

    int jb = g_off[n], je = g_off[n + 1];
    float inv = g_inv[n];

    int j = jb;
    for (; j + 4 <= je; j += 4) {
        unsigned s0 = (unsigned)g_srcs[j];
        unsigned s1 = (unsigned)g_srcs[j + 1];
        unsigned s2 = (unsigned)g_srcs[j + 2];
        unsigned s3 = (unsigned)g_srcs[j + 3];
        uint4 p0 = xin[s0 + slane];
        uint4 p1 = xin[s1 + slane];
        uint4 p2 = xin[s2 + slane];
        uint4 p3 = xin[s3 + slane];
        const __half2* h0 = (const __half2*)&p0;
        const __half2* h1 = (const __half2*)&p1;
        const __half2* h2 = (const __half2*)&p2;
        const __half2* h3 = (const __half2*)&p3;
        #pragma unroll
        for (int q = 0; q < 4; q++) {
            float2 f0 = __half22float2(h0[q]);
            float2 f1 = __half22float2(h1[q]);
            float2 f2 = __half22float2(h2[q]);
            float2 f3 = __half22float2(h3[q]);
            acc[2 * q]     += (f0.x + f1.x) + (f2.x + f3.x);
            acc[2 * q + 1] += (f0.y + f1.y) + (f2.y + f3.y);
        }
    }
    for (; j < je; ++j) {
        uint4 p = xin[(unsigned)g_srcs[j] + slane];
        const __half2* h = (const __half2*)&p;
        #pragma unroll
        for (int q = 0; q < 4; q++) {
            float2 f = __half22float2(h[q]);
            acc[2 * q] += f.x; acc[2 * q + 1] += f.y;
        }
    }

    #pragma unroll
    for (int q = 0; q < 8; q++) acc[q] *= inv;

    // conv halo via width-16 shuffles: need left lane's acc[4..7], right lane's acc[0..3]
    float vv[16];
    #pragma unroll
    for (int q = 0; q < 8; q++) vv[4 + q] = acc[q];
    #pragma unroll
    for (int q = 0; q < 4; q++)
        vv[q] = __shfl_up_sync(0xffffffffu, acc[4 + q], 1, 16);
    #pragma unroll
    for (int q = 0; q < 4; q++)
        vv[12 + q] = __shfl_down_sync(0xffffffffu, acc[q], 1, 16);
    if (slane == 0)  { vv[0] = 0.f; vv[1] = 0.f; vv[2] = 0.f; vv[3] = 0.f; }   // 'same' pad
    if (slane == 15) { vv[12] = 0.f; vv[13] = 0.f; vv[14] = 0.f; vv[15] = 0.f; }

    float res[8];
    #pragma unroll
    for (int i = 0; i < 8; i++) {
        float o = bias;
        #pragma unroll
        for (int k = 0; k < 9; k++) o = fmaf(vv[i + k], w[k], o); // cross-correlation
        res[i] = fmaxf(o, 0.0f);
    }

    uint4 outp;
    unsigned* op = (unsigned*)&outp;
    #pragma unroll
    for (int q = 0; q < 4; q++) {
        __half2 hh = __floats2half2_rn(res[2 * q], res[2 * q + 1]);
        op[q] = *(unsigned*)&hh;
    }
    xout[rbase] = outp;
}

// ---------------- final projection ----------------
// x.reshape(T,N) on row-major [N,T] is a flat reinterpretation:
// out[t,c] = b[c] + sum_n hflat[t*N+n] * W[c*N+n]; both contiguous in n.
#define TTILE 8
#define NCHF 8
__global__ void k_init_out(const float* __restrict__ bo, float* __restrict__ out) {
    int i = threadIdx.x; // 384 = TT*3
    out[i] = __ldg(bo + (i % 3));
}

__global__ void __launch_bounds__(512) k_final(
    const float* __restrict__ W, float* __restrict__ out)
{
    const __half* __restrict__ h = g_hbuf[1];
    int t0 = blockIdx.x * TTILE;
    const int nper = NV / NCHF; // 12500
    int n0 = blockIdx.y * nper;

    float acc[TTILE][3];
    #pragma unroll
    for (int t = 0; t < TTILE; t++)
        #pragma unroll
        for (int c = 0; c < 3; c++) acc[t][c] = 0.f;

    for (int n = n0 + threadIdx.x; n < n0 + nper; n += 512) {
        float w0 = __ldg(W + n);
        float w1 = __ldg(W + NV + n);
        float w2 = __ldg(W + 2 * NV + n);
        #pragma unroll
        for (int t = 0; t < TTILE; t++) {
            float v = __half2float(h[(size_t)(t0 + t) * NV + n]);
            acc[t][0] = fmaf(v, w0, acc[t][0]);
            acc[t][1] = fmaf(v, w1, acc[t][1]);
            acc[t][2] = fmaf(v, w2, acc[t][2]);
        }
    }

    #pragma unroll
    for (int t = 0; t < TTILE; t++)
        #pragma unroll
        for (int c = 0; c < 3; c++)
            #pragma unroll
            for (int o = 16; o; o >>= 1)
                acc[t][c] += __shfl_down_sync(0xffffffffu, acc[t][c], o);

    __shared__ float sh[16][TTILE][3];
    int lane = threadIdx.x & 31, wid = threadIdx.x >> 5;
    if (lane == 0)
        #pragma unroll
        for (int t = 0; t < TTILE; t++)
            #pragma unroll
            for (int c = 0; c < 3; c++) sh[wid][t][c] = acc[t][c];
    __syncthreads();
    // 24 outputs per block: lanes 0..23 of warp 0
    if (wid == 0 && lane < TTILE * 3) {
        int t = lane / 3, c = lane % 3;
        float s = 0.f;
        #pragma unroll
        for (int wgi = 0; wgi < 16; wgi++) s += sh[wgi][t][c];
        atomicAdd(&out[(t0 + t) * 3 + c], s);
    }
}

// ---------------- launch ----------------
extern "C" void kernel_launch(void* const* d_in, const int* in_sizes, int n_in,
                              void* d_out, int out_size)
{
    const float* x  = (const float*)d_in[0];
    const int*   ei = (const int*)d_in[1];
    const float* cw = (const float*)d_in[2]; // [L,1,1,K]
    const float* cb = (const float*)d_in[3]; // [L,1]
    const float* Wo = (const float*)d_in[4]; // [3,N]
    const float* bo = (const float*)d_in[5]; // [3]
    float* out = (float*)d_out;

    int E = in_sizes[1] / 2;
    const int* src = ei;
    const int* dst = ei + E;

    // input fp32 -> fp16 (+ zero deg)
    k_cvt<<<NV * TT / 4 / 256, 256>>>((const float4*)x);

    // CSR by destination (rebuilt every call; deterministic work)
    k_hist<<<(E + 255) / 256, 256>>>(dst, E);
    k_scanA<<<NCHUNK, 1024>>>();
    k_scanC<<<NCHUNK, 1024>>>(E);
    k_scatter<<<(E + 255) / 256, 256>>>(src, dst, E);

    // 3 fused layers: agg -> conv -> relu, ping-pong fp16 buffers
    k_layer<<<NV / 16, 256>>>(0, 1, cw + 0, cb + 0);
    k_layer<<<NV / 16, 256>>>(1, 0, cw + 9, cb + 1);
    k_layer<<<NV / 16, 256>>>(0, 1, cw + 18, cb + 2);

    // final [T,3] projection
    k_init_out<<<1, TT * 3>>>(bo, out);
    k_final<<<dim3(TT / TTILE, NCHF), 512>>>(Wo, out);
}